// round 5
// baseline (speedup 1.0000x reference)
#include <cuda_runtime.h>
#include <math.h>

#define B_ 32
#define T_ 32
#define F_ 64
#define H_ 256
#define N_ 1024
#define A_ 64
#define C_ 192
#define M_ 256
#define NTHREADS 256
#define HSOFF (T_*H_*B_)

// ---------------- persistent state (device globals; no allocation) ----------------
__device__ float g_h[H_*B_];            // h[k*B+b]
__device__ float g_x[T_*F_*B_];         // x[t][f*B+b]
__device__ float g_candH[T_*C_*B_];     // cand_s[c,b]: [(s*C+c)*B+b]
__device__ float g_vH[T_*H_*B_];        // v_s[k,b] = Wq[A:,:]^T cand_s: [(s*H+k)*B+b]
__device__ float g_cb[T_*B_];           // cb_s[b] = cand_s . bq[A:]
__device__ float g_W1[T_*N_*B_];        // w_s: [(s*N+n)*B+b]   (sim reads, lanes=b)
__device__ float g_W2[T_*B_*N_];        // w_s: [(s*B+b)*N+n]   (G dots, coalesced n)
__device__ float g_d[T_*B_];            // d_s[b]
__device__ float g_G[T_*B_];            // G_s[b] (atomic partials)
__device__ float g_P[N_*H_];            // P[n,k] = addr @ Wq[0:64,:]
__device__ float g_pb[N_];              // pb[n] = addr_n . bq[0:64]
__device__ float g_beta[B_];
__device__ float g_gi[3*H_*B_];
__device__ float g_gh[3*H_*B_];
__device__ float g_simT[B_*N_];         // sim (pre-beta): [b*N+n]
__device__ float g_ra[A_*B_];           // reading[0:64]: [a*B+b] (atomic partials)
__device__ float g_rc[C_*B_];           // reading[64:256]: [c*B+b]
__device__ unsigned g_leaf[16];
__device__ unsigned g_root = 0;
__device__ volatile unsigned g_bar_gen = 0;

// ---------------- software grid barrier, tree arrivals ----------------
__device__ __forceinline__ void grid_sync(int nblocks) {
    __syncthreads();
    if (threadIdx.x == 0) {
        __threadfence();
        unsigned gen = g_bar_gen;
        int leaf = blockIdx.x & 15;
        unsigned lsz = (unsigned)(nblocks >> 4) + ((leaf < (nblocks & 15)) ? 1u : 0u);
        if (atomicAdd(&g_leaf[leaf], 1u) == lsz - 1u) {
            atomicExch(&g_leaf[leaf], 0u);
            if (atomicAdd(&g_root, 1u) == 15u) {
                atomicExch(&g_root, 0u);
                __threadfence();
                g_bar_gen = gen + 1u;
            }
        }
        while (g_bar_gen == gen) { __nanosleep(32); }
        __threadfence();
    }
    __syncthreads();
}

__device__ __forceinline__ float warp_sum(float v) {
    #pragma unroll
    for (int o = 16; o; o >>= 1) v += __shfl_xor_sync(0xffffffffu, v, o);
    return v;
}
__device__ __forceinline__ float warp_max(float v) {
    #pragma unroll
    for (int o = 16; o; o >>= 1) v = fmaxf(v, __shfl_xor_sync(0xffffffffu, v, o));
    return v;
}

// warp-cooperative: logits + log_softmax for one (t, b)
__device__ __forceinline__ void write_out(const float* __restrict__ Wout,
                                          const float* __restrict__ bo,
                                          float* __restrict__ out,
                                          int tstep, int b, int lane) {
    float logit[10];
    float mx = -1e30f;
    #pragma unroll
    for (int o = 0; o < 10; o++) {
        float s = 0.f;
        #pragma unroll
        for (int j = 0; j < 8; j++) {
            int k = lane + 32*j;
            s += Wout[o*H_ + k] * g_h[k*B_ + b];
        }
        s = warp_sum(s);
        s += bo[o];
        logit[o] = s;
        mx = fmaxf(mx, s);
    }
    float se = 0.f;
    #pragma unroll
    for (int o = 0; o < 10; o++) se += expf(logit[o] - mx);
    float lse = mx + logf(se);
    if (lane == 0) {
        #pragma unroll
        for (int o = 0; o < 10; o++)
            out[HSOFF + (tstep*10 + o)*B_ + b] = logit[o] - lse;
    }
}

__global__ __launch_bounds__(NTHREADS, 4)
void dntm_kernel(const float* __restrict__ batch,
                 const float* __restrict__ Wi,  const float* __restrict__ bi,
                 const float* __restrict__ Wh,  const float* __restrict__ bh,
                 const float* __restrict__ Wm,  const float* __restrict__ bm,
                 const float* __restrict__ Wout,const float* __restrict__ bo,
                 const float* __restrict__ addr,
                 const float* __restrict__ Wq,  const float* __restrict__ bq,
                 const float* __restrict__ u,
                 const float* __restrict__ Wch, const float* __restrict__ Wci,
                 float* __restrict__ out, int nblocks)
{
    const int tid0 = threadIdx.x;
    const int gt   = blockIdx.x * NTHREADS + tid0;
    const int NT   = nblocks * NTHREADS;
    const int lane = tid0 & 31;
    const int wid  = gt >> 5;
    const int nw   = NT >> 5;
    const int wl   = tid0 >> 5;

    __shared__ float s_red[NTHREADS];
    __shared__ float sw[256];   // chunk softmax weights (cnt <= 256)

    // ---------------- P0: init + precompute x layout, P, pb ----------------
    {
        for (int i = gt; i < H_*B_; i += NT) g_h[i] = 0.f;
        for (int i = gt; i < T_*F_*B_; i += NT) {
            int t   = i / (F_*B_);
            int lin = i - t*(F_*B_);
            int bb  = lin >> 6;
            int ff  = lin & 63;
            g_x[i] = batch[bb*(T_*F_) + t*F_ + ff];
        }
        // P[n,k] = sum_a addr[n,a] * Wq[a*H+k]
        for (int i = gt; i < N_*H_; i += NT) {
            int n = i >> 8, k = i & 255;
            float s = 0.f;
            #pragma unroll 8
            for (int a = 0; a < A_; a++) s += addr[n*A_ + a] * Wq[a*H_ + k];
            g_P[i] = s;
        }
        for (int i = gt; i < N_; i += NT) {
            float s = 0.f;
            #pragma unroll 8
            for (int a = 0; a < A_; a++) s += addr[i*A_ + a] * bq[a];
            g_pb[i] = s;
        }
    }
    grid_sync(nblocks);

    for (int t = 0; t < T_; t++) {
        const float* xt = g_x + t*F_*B_;

        // -- Ph1: gi, gh, cand_t, beta, d_s(s<t); zero G, ra --------------------
        {
            int tot = 57376 + 64*t;
            for (int i = gt; i < tot; i += NT) {
                if (i < 24576) {                            // gi[row,b]
                    int row = i >> 5, b = i & 31;
                    const float* w = Wi + row*F_;
                    float s = bi[row];
                    #pragma unroll 8
                    for (int f = 0; f < F_; f++) s += w[f] * xt[f*B_ + b];
                    g_gi[row*B_ + b] = s;
                } else if (i < 49152) {                     // gh[row,b]
                    int ii = i - 24576; int row = ii >> 5, b = ii & 31;
                    const float* w = Wh + row*H_;
                    float s = bh[row];
                    #pragma unroll 8
                    for (int k = 0; k < H_; k++) s += w[k] * g_h[k*B_ + b];
                    g_gh[row*B_ + b] = s;
                } else if (i < 55296) {                     // cand_t[c,b]
                    int ii = i - 49152; int c = ii >> 5, b = ii & 31;
                    float s = 0.f;
                    #pragma unroll 8
                    for (int k = 0; k < H_; k++) s += Wch[c*H_ + k] * g_h[k*B_ + b];
                    #pragma unroll 8
                    for (int f = 0; f < F_; f++) s += Wci[c*F_ + f] * xt[f*B_ + b];
                    g_candH[(t*C_ + c)*B_ + b] = fmaxf(s, 0.f);
                } else if (i < 55328) {                     // beta[b]
                    int b = i - 55296;
                    float s = 0.f;
                    #pragma unroll 8
                    for (int k = 0; k < H_; k++) s += u[k] * g_h[k*B_ + b];
                    float sp = (s > 0.f) ? s + log1pf(expf(-s)) : log1pf(expf(s));
                    g_beta[b] = sp + 1.f;
                } else if (i < 55328 + 32*t) {              // d_s[b] = v_s.h + cb_s
                    int ii = i - 55328; int s = ii >> 5, b = ii & 31;
                    float acc = g_cb[s*B_ + b];
                    const float* vs = g_vH + s*H_*B_;
                    #pragma unroll 8
                    for (int k = 0; k < H_; k++) acc += vs[k*B_ + b] * g_h[k*B_ + b];
                    g_d[s*B_ + b] = acc;
                } else if (i < 55328 + 64*t) {              // zero G[s<t]
                    g_G[i - 55328 - 32*t] = 0.f;
                } else {                                    // zero ra (2048)
                    g_ra[i - 55328 - 64*t] = 0.f;
                }
            }
        }
        grid_sync(nblocks);

        // -- Ph2: sim -> simT[b][n];  v_t, cb_t;  out head for t-1 --------------
        {
            if (gt < 32768) {                               // warp per n, lanes = b
                int n = wid;  int b = lane;
                float acc = g_pb[n];
                const float* Pn = g_P + n*H_;
                #pragma unroll 8
                for (int k = 0; k < H_; k++) acc += Pn[k] * g_h[k*B_ + b];
                for (int s = 0; s < t; s++)
                    acc += g_W1[(s*N_ + n)*B_ + b] * g_d[s*B_ + b];
                g_simT[b*N_ + n] = acc;                     // scattered 4B store
            } else if (gt < 41024) {
                int idx = gt - 32768;
                if (idx < 8192) {                           // v_t[k,b]
                    int k = idx >> 5, b = idx & 31;
                    float s = 0.f;
                    #pragma unroll 8
                    for (int c = 0; c < C_; c++)
                        s += Wq[(A_ + c)*H_ + k] * g_candH[(t*C_ + c)*B_ + b];
                    g_vH[(t*H_ + k)*B_ + b] = s;
                } else {                                    // cb_t[b]
                    int b = idx - 8192;
                    float s = 0.f;
                    #pragma unroll 8
                    for (int c = 0; c < C_; c++)
                        s += g_candH[(t*C_ + c)*B_ + b] * bq[A_ + c];
                    g_cb[t*B_ + b] = s;
                }
            }
            if (t > 0 && wid >= 1312 && wid < 1344)
                write_out(Wout, bo, out, t - 1, wid - 1312, lane);
        }
        grid_sync(nblocks);

        // -- Ph3: per-(b,chunk) block: stats, w -> W1/W2, partial G, partial ra --
        {
            int NCH = nblocks >> 5;
            if (blockIdx.x < (NCH << 5)) {
                int b    = blockIdx.x & 31;
                int chk  = blockIdx.x >> 5;
                int CH   = (N_ + NCH - 1) / NCH;
                int nbeg = chk * CH;
                int nend = nbeg + CH; if (nend > N_) nend = N_;
                int cnt  = nend - nbeg;
                float bs = g_beta[b];
                const float* simb = g_simT + b*N_;

                // softmax stats over bs*sim[b][:]
                float v0 = bs * simb[tid0      ];
                float v1 = bs * simb[tid0 + 256];
                float v2 = bs * simb[tid0 + 512];
                float v3 = bs * simb[tid0 + 768];
                float m = fmaxf(fmaxf(v0, v1), fmaxf(v2, v3));
                m = warp_max(m);
                if (lane == 0) s_red[wl] = m;
                __syncthreads();
                float mb = s_red[0];
                #pragma unroll
                for (int w = 1; w < 8; w++) mb = fmaxf(mb, s_red[w]);
                float e = expf(v0 - mb) + expf(v1 - mb) + expf(v2 - mb) + expf(v3 - mb);
                e = warp_sum(e);
                __syncthreads();
                if (lane == 0) s_red[wl] = e;
                __syncthreads();
                float ss = 0.f;
                #pragma unroll
                for (int w = 0; w < 8; w++) ss += s_red[w];
                float li = 1.f / ss;
                __syncthreads();

                // stage B: w for this chunk -> smem + W1 + W2
                if (cnt > 0 && tid0 < cnt) {
                    int n = nbeg + tid0;
                    float w = expf(bs * simb[n] - mb) * li;
                    sw[tid0] = w;
                    g_W1[(t*N_ + n)*B_ + b] = w;
                    g_W2[(t*B_ + b)*N_ + n] = w;
                }
                __syncthreads();

                // stage C1: partial G_s = sum_{chunk} w_t * w_s
                for (int s = wl; s < t; s += 8) {
                    const float* w2s = g_W2 + (s*B_ + b)*N_ + nbeg;
                    float gp = 0.f;
                    for (int j = lane; j < cnt; j += 32) gp += sw[j] * w2s[j];
                    gp = warp_sum(gp);
                    if (lane == 0) atomicAdd(&g_G[s*B_ + b], gp);
                }

                // stage C2: partial ra[a] = sum_{chunk} w_t[n] addr[n,a]
                float a0 = 0.f, a1 = 0.f;
                for (int j = wl; j < cnt; j += 8) {
                    float w = sw[j];
                    const float* ar = addr + (nbeg + j)*A_;
                    a0 += w * ar[lane];
                    a1 += w * ar[lane + 32];
                }
                s_red[tid0] = 0.f;
                __syncthreads();
                atomicAdd(&s_red[lane], a0);
                atomicAdd(&s_red[lane + 32], a1);
                __syncthreads();
                if (tid0 < A_) atomicAdd(&g_ra[tid0*B_ + b], s_red[tid0]);
            }
        }
        grid_sync(nblocks);

        // -- Ph4: rc[c,b] = sum_{s<t} G_s[b] * cand_s[c,b] ----------------------
        {
            if (gt < C_*B_) {
                int c = gt >> 5, b = gt & 31;
                float acc = 0.f;
                for (int s = 0; s < t; s++)
                    acc += g_G[s*B_ + b] * g_candH[(s*C_ + c)*B_ + b];
                g_rc[c*B_ + b] = acc;
            }
        }
        grid_sync(nblocks);

        // -- Ph5: gm + GRU update + hs write ------------------------------------
        for (int it = wid; it < H_*B_; it += nw) {
            int hid = it >> 5, b = it & 31;
            const float* w0 = Wm + hid*M_;
            const float* w1 = Wm + (H_ + hid)*M_;
            const float* w2 = Wm + (2*H_ + hid)*M_;
            float s0 = 0.f, s1 = 0.f, s2 = 0.f;
            #pragma unroll
            for (int j = 0; j < 8; j++) {
                int m = lane + 32*j;
                float rv = (m < A_) ? g_ra[m*B_ + b] : g_rc[(m - A_)*B_ + b];
                s0 += w0[m]*rv; s1 += w1[m]*rv; s2 += w2[m]*rv;
            }
            s0 = warp_sum(s0); s1 = warp_sum(s1); s2 = warp_sum(s2);
            if (lane == 0) {
                int gb = hid*B_ + b;
                float gm0 = s0 + bm[hid];
                float gm1 = s1 + bm[H_ + hid];
                float gm2 = s2 + bm[2*H_ + hid];
                float r  = 1.f / (1.f + expf(-(g_gi[gb] + g_gh[gb] + gm0)));
                float z  = 1.f / (1.f + expf(-(g_gi[H_*B_ + gb] + g_gh[H_*B_ + gb] + gm1)));
                float nn = tanhf(g_gi[2*H_*B_ + gb] + gm2 + r * g_gh[2*H_*B_ + gb]);
                float hn = (1.f - z)*nn + z*g_h[gb];
                g_h[gb] = hn;
                out[t*H_*B_ + gb] = hn;
            }
        }
        grid_sync(nblocks);
    }

    // final timestep's output head
    if (wid < B_) write_out(Wout, bo, out, T_ - 1, wid, lane);
}

extern "C" void kernel_launch(void* const* d_in, const int* in_sizes, int n_in,
                              void* d_out, int out_size) {
    (void)in_sizes; (void)n_in; (void)out_size;
    const float* batch = (const float*)d_in[0];
    const float* Wi    = (const float*)d_in[1];
    const float* bi    = (const float*)d_in[2];
    const float* Wh    = (const float*)d_in[3];
    const float* bh    = (const float*)d_in[4];
    const float* Wm    = (const float*)d_in[5];
    const float* bm    = (const float*)d_in[6];
    const float* Wout  = (const float*)d_in[7];
    const float* bo    = (const float*)d_in[8];
    const float* addr  = (const float*)d_in[9];
    const float* Wq    = (const float*)d_in[10];
    const float* bq    = (const float*)d_in[11];
    const float* u     = (const float*)d_in[12];
    const float* Wch   = (const float*)d_in[13];
    const float* Wci   = (const float*)d_in[14];
    float* out = (float*)d_out;

    int dev = 0;
    cudaGetDevice(&dev);
    int sms = 148;
    cudaDeviceGetAttribute(&sms, cudaDevAttrMultiProcessorCount, dev);
    int occ = 1;
    cudaOccupancyMaxActiveBlocksPerMultiprocessor(&occ, dntm_kernel, NTHREADS, 0);
    if (occ < 1) occ = 1;
    if (occ > 4) occ = 4;
    int grid = sms * occ;

    dntm_kernel<<<grid, NTHREADS>>>(batch, Wi, bi, Wh, bh, Wm, bm, Wout, bo,
                                    addr, Wq, bq, u, Wch, Wci, out, grid);
}

// round 6
// speedup vs baseline: 1.1883x; 1.1883x over previous
#include <cuda_runtime.h>
#include <math.h>

#define B_ 32
#define T_ 32
#define F_ 64
#define H_ 256
#define N_ 1024
#define A_ 64
#define C_ 192
#define M_ 256
#define NTHR 1024
#define HSOFF (T_*H_*B_)

// ---------------- persistent state ----------------
__device__ __align__(16) float g_h[H_*B_];        // h[k*32+b]
__device__ __align__(16) float g_hT[B_*H_];       // h[b*256+k]
__device__ __align__(16) float g_x[T_*F_*B_];     // x[t][f*32+b]
__device__ __align__(16) float g_content[B_*N_*C_];
__device__ __align__(16) float g_candH[T_*C_*B_]; // [(t*192+c)*32+b]
__device__ __align__(16) float g_v[T_*B_*H_];     // [(s*32+b)*256+k]
__device__ float g_cb[T_*B_];
__device__ __align__(16) float g_W1[T_*B_*N_];    // [(s*32+b)*1024+n]
__device__ __align__(16) float g_PT[H_*N_];       // PT[k*1024+n] = P[n,k]
__device__ __align__(16) float g_pb[N_];
__device__ float g_beta[B_];
__device__ __align__(16) float g_gi[3*H_*B_];
__device__ __align__(16) float g_gh[3*H_*B_];
__device__ __align__(16) float g_simT[B_*N_];     // raw sim (pre-beta), [b*1024+n]
__device__ __align__(16) float g_r[M_*B_];        // reading[m*32+b]
__device__ unsigned g_leaf[8];
__device__ unsigned g_root = 0;
__device__ volatile unsigned g_bar_gen = 0;

// ---------------- grid barrier (tree arrivals) ----------------
__device__ __forceinline__ void grid_sync(int nblocks) {
    __syncthreads();
    if (threadIdx.x == 0) {
        __threadfence();
        unsigned gen = g_bar_gen;
        int leaf = blockIdx.x & 7;
        unsigned lsz = (unsigned)(nblocks >> 3) + ((leaf < (nblocks & 7)) ? 1u : 0u);
        if (atomicAdd(&g_leaf[leaf], 1u) == lsz - 1u) {
            atomicExch(&g_leaf[leaf], 0u);
            if (atomicAdd(&g_root, 1u) == 7u) {
                atomicExch(&g_root, 0u);
                __threadfence();
                g_bar_gen = gen + 1u;
            }
        }
        while (g_bar_gen == gen) { __nanosleep(32); }
        __threadfence();
    }
    __syncthreads();
}

__device__ __forceinline__ float warp_sum(float v) {
    #pragma unroll
    for (int o = 16; o; o >>= 1) v += __shfl_xor_sync(0xffffffffu, v, o);
    return v;
}
__device__ __forceinline__ float warp_max(float v) {
    #pragma unroll
    for (int o = 16; o; o >>= 1) v = fmaxf(v, __shfl_xor_sync(0xffffffffu, v, o));
    return v;
}

__device__ __forceinline__ void write_out(const float* __restrict__ Wout,
                                          const float* __restrict__ bo,
                                          float* __restrict__ out,
                                          int tstep, int b, int lane) {
    float logit[10];
    float mx = -1e30f;
    #pragma unroll
    for (int o = 0; o < 10; o++) {
        float s = 0.f;
        #pragma unroll
        for (int j = 0; j < 8; j++) {
            int k = lane + 32*j;
            s += Wout[o*H_ + k] * g_h[k*B_ + b];
        }
        s = warp_sum(s);
        s += bo[o];
        logit[o] = s;
        mx = fmaxf(mx, s);
    }
    float se = 0.f;
    #pragma unroll
    for (int o = 0; o < 10; o++) se += expf(logit[o] - mx);
    float lse = mx + logf(se);
    if (lane == 0) {
        #pragma unroll
        for (int o = 0; o < 10; o++)
            out[HSOFF + (tstep*10 + o)*B_ + b] = logit[o] - lse;
    }
}

__global__ __launch_bounds__(NTHR, 1)
void dntm_kernel(const float* __restrict__ batch,
                 const float* __restrict__ Wi,  const float* __restrict__ bi,
                 const float* __restrict__ Wh,  const float* __restrict__ bh,
                 const float* __restrict__ Wm,  const float* __restrict__ bm,
                 const float* __restrict__ Wout,const float* __restrict__ bo,
                 const float* __restrict__ addr,
                 const float* __restrict__ Wq,  const float* __restrict__ bq,
                 const float* __restrict__ u,
                 const float* __restrict__ Wch, const float* __restrict__ Wci,
                 float* __restrict__ out, int nblocks)
{
    const int blk  = blockIdx.x;
    const int tid  = threadIdx.x;
    const int lane = tid & 31;
    const int wl   = tid >> 5;
    const int gt   = blk * NTHR + tid;
    const int GT   = nblocks * NTHR;

    __shared__ __align__(16) float smem[10304];   // ~40 KB
    float4* s4 = (float4*)smem;

    // ---------------- P0: init ----------------
    {
        float4 z4 = make_float4(0.f,0.f,0.f,0.f);
        float4* c4 = (float4*)g_content;
        for (int i = gt; i < (B_*N_*C_)/4; i += GT) c4[i] = z4;
        for (int i = gt; i < H_*B_; i += GT) { g_h[i] = 0.f; g_hT[i] = 0.f; }
        for (int i = gt; i < T_*F_*B_; i += GT) {
            int t   = i / (F_*B_);
            int lin = i - t*(F_*B_);
            int bb  = lin >> 6, ff = lin & 63;
            g_x[i] = batch[bb*(T_*F_) + t*F_ + ff];
        }
        // PT[k][n] = sum_a addr[n,a]*Wq[a*256+k]; warp-unit = (n, kgroup)
        int gw = blk*32 + wl;
        for (int wu = gw; wu < N_*8; wu += nblocks*32) {
            int n = wu >> 3, k0 = (wu & 7) << 5;
            float acc = 0.f;
            #pragma unroll 8
            for (int a = 0; a < A_; a++) acc += addr[n*A_ + a] * Wq[a*H_ + k0 + lane];
            g_PT[(k0 + lane)*N_ + n] = acc;
        }
        for (int i = gt; i < N_; i += GT) {
            float s = 0.f;
            #pragma unroll 8
            for (int a = 0; a < A_; a++) s += addr[i*A_ + a] * bq[a];
            g_pb[i] = s;
        }
    }
    grid_sync(nblocks);

    for (int t = 0; t < T_; t++) {

        // ================= PHASE A =================
        if (blk < 16) {
            // ---- sim for b0, b0+1 ----
            int b0 = blk*2;
            const float4* hT4 = (const float4*)g_hT;
            if (tid < 128) s4[tid] = hT4[b0*64 + tid];     // s_h[2][256]
            __syncthreads();
            float* s_d = smem + 512;
            for (int idx = wl; idx < 2*t; idx += 32) {
                int s = idx >> 1, bl = idx & 1;
                const float* vrow = g_v + (s*B_ + b0 + bl)*H_;
                float acc = 0.f;
                #pragma unroll
                for (int j = 0; j < 8; j++)
                    acc += vrow[lane + 32*j] * smem[bl*256 + lane + 32*j];
                acc = warp_sum(acc);
                if (lane == 0) s_d[idx] = acc + g_cb[s*B_ + b0 + bl];
            }
            __syncthreads();
            int p = wl >> 1, kh = wl & 1;
            int b_l = p >> 3, b = b0 + b_l, ng = p & 7;
            float a0, a1, a2, a3;
            if (kh == 0) {
                float4 pbv = ((const float4*)g_pb)[ng*32 + lane];
                a0 = pbv.x; a1 = pbv.y; a2 = pbv.z; a3 = pbv.w;
                for (int s = 0; s < t; s++) {
                    float4 w1 = ((const float4*)g_W1)[(s*B_ + b)*256 + ng*32 + lane];
                    float dv = s_d[s*2 + b_l];
                    a0 += w1.x*dv; a1 += w1.y*dv; a2 += w1.z*dv; a3 += w1.w*dv;
                }
            } else { a0 = a1 = a2 = a3 = 0.f; }
            const float4* pt4 = (const float4*)g_PT;
            const float* hb = smem + b_l*256;
            int kbeg = kh << 7;
            #pragma unroll 4
            for (int k = kbeg; k < kbeg + 128; k++) {
                float4 pv = pt4[k*256 + ng*32 + lane];
                float hk = hb[k];
                a0 += pv.x*hk; a1 += pv.y*hk; a2 += pv.z*hk; a3 += pv.w*hk;
            }
            float* s_acc = smem + 576;
            if (kh == 1) {
                s_acc[p*128 + lane*4    ] = a0;
                s_acc[p*128 + lane*4 + 1] = a1;
                s_acc[p*128 + lane*4 + 2] = a2;
                s_acc[p*128 + lane*4 + 3] = a3;
            }
            __syncthreads();
            if (kh == 0) {
                a0 += s_acc[p*128 + lane*4    ];
                a1 += s_acc[p*128 + lane*4 + 1];
                a2 += s_acc[p*128 + lane*4 + 2];
                a3 += s_acc[p*128 + lane*4 + 3];
                float4 o = make_float4(a0, a1, a2, a3);
                ((float4*)g_simT)[b*256 + ng*32 + lane] = o;
            }
        } else if (blk < 71) {
            // ---- gates: stage h (8192) + x_t (2048) in smem ----
            const float4* h4 = (const float4*)g_h;
            const float4* x4 = (const float4*)g_x + t*512;
            for (int i = tid; i < 2560; i += NTHR) s4[i] = (i < 2048) ? h4[i] : x4[i - 2048];
            __syncthreads();
            int uu = (blk - 16)*32 + wl;
            int b = lane;
            if (uu < 768) {                                   // gh row
                const float4* w4 = (const float4*)Wh + uu*64;
                float acc = bh[uu];
                #pragma unroll 8
                for (int kk = 0; kk < 64; kk++) {
                    float4 w = w4[kk];
                    acc += w.x*smem[(kk*4  )*32 + b] + w.y*smem[(kk*4+1)*32 + b]
                         + w.z*smem[(kk*4+2)*32 + b] + w.w*smem[(kk*4+3)*32 + b];
                }
                g_gh[uu*32 + b] = acc;
            } else if (uu < 1536) {                           // gi row
                int row = uu - 768;
                const float4* w4 = (const float4*)Wi + row*16;
                float acc = bi[row];
                #pragma unroll
                for (int ff = 0; ff < 16; ff++) {
                    float4 w = w4[ff];
                    acc += w.x*smem[8192 + (ff*4  )*32 + b] + w.y*smem[8192 + (ff*4+1)*32 + b]
                         + w.z*smem[8192 + (ff*4+2)*32 + b] + w.w*smem[8192 + (ff*4+3)*32 + b];
                }
                g_gi[row*32 + b] = acc;
            } else if (uu < 1728) {                           // cand row
                int c = uu - 1536;
                const float4* wh4 = (const float4*)Wch + c*64;
                const float4* wx4 = (const float4*)Wci + c*16;
                float acc = 0.f;
                #pragma unroll 8
                for (int kk = 0; kk < 64; kk++) {
                    float4 w = wh4[kk];
                    acc += w.x*smem[(kk*4  )*32 + b] + w.y*smem[(kk*4+1)*32 + b]
                         + w.z*smem[(kk*4+2)*32 + b] + w.w*smem[(kk*4+3)*32 + b];
                }
                #pragma unroll
                for (int ff = 0; ff < 16; ff++) {
                    float4 w = wx4[ff];
                    acc += w.x*smem[8192 + (ff*4  )*32 + b] + w.y*smem[8192 + (ff*4+1)*32 + b]
                         + w.z*smem[8192 + (ff*4+2)*32 + b] + w.w*smem[8192 + (ff*4+3)*32 + b];
                }
                g_candH[(t*C_ + c)*32 + b] = fmaxf(acc, 0.f);
            } else if (uu == 1728) {                          // beta
                const float4* u4 = (const float4*)u;
                float acc = 0.f;
                #pragma unroll 8
                for (int kk = 0; kk < 64; kk++) {
                    float4 w = u4[kk];
                    acc += w.x*smem[(kk*4  )*32 + b] + w.y*smem[(kk*4+1)*32 + b]
                         + w.z*smem[(kk*4+2)*32 + b] + w.w*smem[(kk*4+3)*32 + b];
                }
                float sp = (acc > 0.f) ? acc + log1pf(expf(-acc)) : log1pf(expf(acc));
                g_beta[b] = sp + 1.f;
            }
        } else if (blk == 71) {
            if (t > 0) write_out(Wout, bo, out, t - 1, wl, lane);
        } else if (blk == 72) {
            for (int i = tid; i < M_*B_; i += NTHR) g_r[i] = 0.f;
        }
        grid_sync(nblocks);

        // ================= PHASE B =================
        if (blk < 128) {
            int b = blk >> 2, chunk = blk & 3, nbeg = chunk << 8;
            float bs = g_beta[b];
            float v = bs * g_simT[b*N_ + tid];
            float* sm    = smem;
            float* s_w   = smem + 64;
            float* s_red = smem + 320;
            float m = warp_max(v);
            if (lane == 0) sm[wl] = m;
            __syncthreads();
            float mb = sm[0];
            #pragma unroll
            for (int w = 1; w < 32; w++) mb = fmaxf(mb, sm[w]);
            float e = expf(v - mb);
            float es = warp_sum(e);
            __syncthreads();
            if (lane == 0) sm[wl] = es;
            __syncthreads();
            float ss = 0.f;
            #pragma unroll
            for (int w = 0; w < 32; w++) ss += sm[w];
            float li = 1.f / ss;
            int nl = tid - nbeg;
            if (nl >= 0 && nl < 256) {
                float wv = e * li;
                s_w[nl] = wv;
                g_W1[(t*B_ + b)*N_ + tid] = wv;
            }
            __syncthreads();
            float candreg[6];
            #pragma unroll
            for (int j = 0; j < 6; j++)
                candreg[j] = g_candH[(t*C_ + lane + 32*j)*32 + b];
            float racc[6] = {0.f,0.f,0.f,0.f,0.f,0.f};
            float aa0 = 0.f, aa1 = 0.f;
            #pragma unroll 2
            for (int i = 0; i < 8; i++) {
                int n = nbeg + wl*8 + i;
                float wv = s_w[wl*8 + i];
                aa0 += wv * addr[n*A_ + lane];
                aa1 += wv * addr[n*A_ + 32 + lane];
                float* crow = g_content + (b*N_ + n)*C_;
                #pragma unroll
                for (int j = 0; j < 6; j++) {
                    float cv = crow[lane + 32*j];
                    racc[j] += wv * cv;
                    crow[lane + 32*j] = cv + wv * candreg[j];
                }
            }
            if (tid < 256) s_red[tid] = 0.f;
            __syncthreads();
            atomicAdd(&s_red[lane], aa0);
            atomicAdd(&s_red[lane + 32], aa1);
            #pragma unroll
            for (int j = 0; j < 6; j++) atomicAdd(&s_red[64 + lane + 32*j], racc[j]);
            __syncthreads();
            if (tid < 256) atomicAdd(&g_r[tid*32 + b], s_red[tid]);
        }
        grid_sync(nblocks);

        // ================= PHASE C =================
        if (blk < 16) {
            // gm + GRU for 16 hid rows
            const float4* r4 = (const float4*)g_r;
            for (int i = tid; i < 2048; i += NTHR) s4[i] = r4[i];
            __syncthreads();
            int p = wl >> 1, kh = wl & 1;
            int hid = blk*16 + p, b = lane;
            const float4* wm4 = (const float4*)Wm;
            float acc0, acc1, acc2;
            if (kh == 0) { acc0 = bm[hid]; acc1 = bm[H_ + hid]; acc2 = bm[2*H_ + hid]; }
            else { acc0 = acc1 = acc2 = 0.f; }
            int mbeg = kh << 5;
            #pragma unroll 4
            for (int mm = mbeg; mm < mbeg + 32; mm++) {
                float r0 = smem[(mm*4  )*32 + b], r1 = smem[(mm*4+1)*32 + b];
                float r2 = smem[(mm*4+2)*32 + b], r3 = smem[(mm*4+3)*32 + b];
                float4 w0 = wm4[hid*64 + mm];
                float4 w1 = wm4[(H_ + hid)*64 + mm];
                float4 w2 = wm4[(2*H_ + hid)*64 + mm];
                acc0 += w0.x*r0 + w0.y*r1 + w0.z*r2 + w0.w*r3;
                acc1 += w1.x*r0 + w1.y*r1 + w1.z*r2 + w1.w*r3;
                acc2 += w2.x*r0 + w2.y*r1 + w2.z*r2 + w2.w*r3;
            }
            float* s_c = smem + 8192;
            if (kh == 1) {
                s_c[(p*3    )*32 + b] = acc0;
                s_c[(p*3 + 1)*32 + b] = acc1;
                s_c[(p*3 + 2)*32 + b] = acc2;
            }
            __syncthreads();
            if (kh == 0) {
                acc0 += s_c[(p*3    )*32 + b];
                acc1 += s_c[(p*3 + 1)*32 + b];
                acc2 += s_c[(p*3 + 2)*32 + b];
                int gb = hid*32 + b;
                float r  = 1.f / (1.f + expf(-(g_gi[gb] + g_gh[gb] + acc0)));
                float z  = 1.f / (1.f + expf(-(g_gi[H_*B_ + gb] + g_gh[H_*B_ + gb] + acc1)));
                float nn = tanhf(g_gi[2*H_*B_ + gb] + acc2 + r * g_gh[2*H_*B_ + gb]);
                float hn = (1.f - z)*nn + z*g_h[gb];
                g_h[gb] = hn;
                g_hT[b*H_ + hid] = hn;
                out[t*H_*B_ + gb] = hn;
            }
        } else if (blk < 20) {
            // v_t for 8 b's
            int b0v = (blk - 16)*8;
            const float4* c4 = (const float4*)g_candH + t*1536;
            for (int i = tid; i < 1536; i += NTHR) s4[i] = c4[i];
            __syncthreads();
            int bl = wl >> 2, b = b0v + bl;
            int kh = (wl >> 1) & 1, ch = wl & 1;
            float a0 = 0.f, a1 = 0.f, a2 = 0.f, a3 = 0.f;
            const float4* wq4 = (const float4*)Wq;
            int cbeg = ch*96;
            #pragma unroll 4
            for (int c = cbeg; c < cbeg + 96; c++) {
                float4 w = wq4[(A_ + c)*64 + kh*32 + lane];
                float cv = smem[c*32 + b];
                a0 += w.x*cv; a1 += w.y*cv; a2 += w.z*cv; a3 += w.w*cv;
            }
            float* s_v = smem + 6144;
            int pidx = wl >> 1;
            if (ch == 1) {
                s_v[pidx*128 + lane*4    ] = a0;
                s_v[pidx*128 + lane*4 + 1] = a1;
                s_v[pidx*128 + lane*4 + 2] = a2;
                s_v[pidx*128 + lane*4 + 3] = a3;
            }
            __syncthreads();
            if (ch == 0) {
                a0 += s_v[pidx*128 + lane*4    ];
                a1 += s_v[pidx*128 + lane*4 + 1];
                a2 += s_v[pidx*128 + lane*4 + 2];
                a3 += s_v[pidx*128 + lane*4 + 3];
                float4 o = make_float4(a0, a1, a2, a3);
                ((float4*)g_v)[(t*B_ + b)*64 + kh*32 + lane] = o;
            }
        } else if (blk == 20) {
            int b = wl;
            float acc = 0.f;
            #pragma unroll
            for (int j = 0; j < 6; j++) {
                int c = lane + 32*j;
                acc += g_candH[(t*C_ + c)*32 + b] * bq[A_ + c];
            }
            acc = warp_sum(acc);
            if (lane == 0) g_cb[t*B_ + b] = acc;
        }
        grid_sync(nblocks);
    }

    if (blk == 0) write_out(Wout, bo, out, T_ - 1, wl, lane);
}

extern "C" void kernel_launch(void* const* d_in, const int* in_sizes, int n_in,
                              void* d_out, int out_size) {
    (void)in_sizes; (void)n_in; (void)out_size;
    const float* batch = (const float*)d_in[0];
    const float* Wi    = (const float*)d_in[1];
    const float* bi    = (const float*)d_in[2];
    const float* Wh    = (const float*)d_in[3];
    const float* bh    = (const float*)d_in[4];
    const float* Wm    = (const float*)d_in[5];
    const float* bm    = (const float*)d_in[6];
    const float* Wout  = (const float*)d_in[7];
    const float* bo    = (const float*)d_in[8];
    const float* addr  = (const float*)d_in[9];
    const float* Wq    = (const float*)d_in[10];
    const float* bq    = (const float*)d_in[11];
    const float* u     = (const float*)d_in[12];
    const float* Wch   = (const float*)d_in[13];
    const float* Wci   = (const float*)d_in[14];
    float* out = (float*)d_out;

    int dev = 0;
    cudaGetDevice(&dev);
    int sms = 148;
    cudaDeviceGetAttribute(&sms, cudaDevAttrMultiProcessorCount, dev);
    int grid = sms;                  // 1 block/SM, co-residency guaranteed

    dntm_kernel<<<grid, NTHR>>>(batch, Wi, bi, Wh, bh, Wm, bm, Wout, bo,
                                addr, Wq, bq, u, Wch, Wci, out, grid);
}